// round 7
// baseline (speedup 1.0000x reference)
#include <cuda_runtime.h>
#include <stdint.h>

// Problem constants (fixed by the dataset)
#define NN     10000      // nodes
#define EE     1000       // hyperedges
#define TT     29         // STEPS - 1 transition steps
#define NROWS  (TT * EE)  // 29000 H rows
#define ROWCAP 64         // per-row nonzero capacity (Binom(10000,0.001): P(>64)~0)
#define NSIM   16         // blocks dedicated to the sequential simulation
#define NEXT   264        // extraction blocks (2 per SM-ish)
#define NBLK   (NSIM + NEXT)
#define TPB    256
#define ROWF4  (NN / 4)   // 2500 float4 per H row
#define CHUNK  8          // float4 per lane per chunk (32*8 = 256 float4/chunk)
#define NCHUNK 10         // chunks per row (10*256 >= 2500)
#define NWARP  (NEXT * (TPB / 32))   // 2112 extraction warps

// ---------------- device scratch (no allocations allowed) ----------------
__device__ unsigned short g_list[(size_t)NROWS * ROWCAP]; // node ids per row
__device__ unsigned g_rowcnt[NROWS];   // nonzeros per row
__device__ float    g_z[NN];           // z = H^T (H @ infected)
__device__ float    g_inf[NN];         // infected vector (0/1)
__device__ uint2    g_k1[TT];          // per-step uniform keys (u1)
__device__ uint2    g_k2[TT];          // per-step uniform keys (u2)
__device__ unsigned g_rows_done[TT];   // extraction progress per step (release flag)
__device__ unsigned g_bar_cnt;         // sim grid barrier: arrivals (monotonic)
__device__ unsigned g_bar_gen;         // sim grid barrier: released generation

// ---------------- JAX Threefry-2x32 (exact replica) ----------------
__device__ __forceinline__ void tf2x32(unsigned k0, unsigned k1,
                                       unsigned x0, unsigned x1,
                                       unsigned &o0, unsigned &o1) {
    unsigned ks2 = k0 ^ k1 ^ 0x1BD11BDAu;
    x0 += k0; x1 += k1;
#define ROTL(v,d) (((v) << (d)) | ((v) >> (32 - (d))))
#define RND(r) { x0 += x1; x1 = ROTL(x1, r); x1 ^= x0; }
    RND(13) RND(15) RND(26) RND(6)
    x0 += k1;  x1 += ks2 + 1u;
    RND(17) RND(29) RND(16) RND(24)
    x0 += ks2; x1 += k0 + 2u;
    RND(13) RND(15) RND(26) RND(6)
    x0 += k0;  x1 += k1 + 3u;
    RND(17) RND(29) RND(16) RND(24)
    x0 += k1;  x1 += ks2 + 4u;
    RND(13) RND(15) RND(26) RND(6)
    x0 += ks2; x1 += k0 + 5u;
    o0 = x0; o1 = x1;
#undef RND
#undef ROTL
}

__device__ __forceinline__ float bits_to_uniform(unsigned bits) {
    return __uint_as_float((bits >> 9) | 0x3F800000u) - 1.0f;
}

// ---------------- init: copy t=0 rows, key chain, reset all scratch ----------------
__global__ void k_init(const float* __restrict__ x, float* __restrict__ out) {
    int gid = blockIdx.x * blockDim.x + threadIdx.x;
    if (gid < NN * 3) {
        float v = x[gid];
        out[gid] = v;                                 // pathogen[0] = x
        out[(size_t)30 * NN * 3 + gid] = v;           // state[0]    = x
    }
    if (gid < NN) {
        g_z[gid]   = 0.0f;
        g_inf[gid] = x[gid * 3 + 1];
    }
    if (gid < TT) g_rows_done[gid] = 0u;
    if (gid == 0) {
        g_bar_cnt = 0u; g_bar_gen = 0u;
        // key chain: jax.random.key(42) -> (0, 42); partitionable split:
        // key_i = threefry(key, (0, i)) full output; new carry = i=0.
        unsigned kh = 0u, kl = 42u;
        for (int t = 0; t < TT; t++) {
            unsigned a0, a1, b0, b1, c0, c1;
            tf2x32(kh, kl, 0u, 0u, a0, a1);
            tf2x32(kh, kl, 0u, 1u, b0, b1);
            tf2x32(kh, kl, 0u, 2u, c0, c1);
            g_k1[t] = make_uint2(b0, b1);
            g_k2[t] = make_uint2(c0, c1);
            kh = a0; kl = a1;
        }
    }
}

// ---------------- sim-side grid barrier (NSIM blocks, sense counting) ----------------
__device__ __forceinline__ void sim_barrier(unsigned &gen) {
    __syncthreads();
    gen += 1u;
    if (threadIdx.x == 0) {
        __threadfence();                                   // release my writes
        unsigned a = atomicAdd(&g_bar_cnt, 1u) + 1u;
        if (a == gen * NSIM) {
            atomicExch(&g_bar_gen, gen);                   // release generation
        } else {
            while (atomicAdd(&g_bar_gen, 0u) < gen) __nanosleep(64);
        }
        __threadfence();                                   // acquire others' writes
    }
    __syncthreads();
}

// ---------------- producer role: warp-autonomous row extraction ----------------
// One warp per row; compaction counter is a warp-uniform register (ballot+popc).
// No shared memory, no block syncs, no work-grab atomics: warps free-run, so the
// SM always has warps in their load phase (high memory duty cycle).
__device__ void do_extract(const float* __restrict__ H) {
    const unsigned lane = threadIdx.x & 31u;
    const int ew = (int)(blockIdx.x - NSIM) * (TPB / 32) + (int)(threadIdx.x >> 5);

    for (int r = ew; r < NROWS; r += NWARP) {
        const float4* row = reinterpret_cast<const float4*>(H + (size_t)r * NN);
        unsigned short* lp = g_list + (size_t)r * ROWCAP;
        unsigned cnt = 0u;   // warp-uniform

        for (int c = 0; c < NCHUNK; c++) {
            int b0 = c * (32 * CHUNK);
            // Front-batched loads: MLP = 8 per lane.
            float4 buf[CHUNK];
#pragma unroll
            for (int k = 0; k < CHUNK; k++) {
                int idx = b0 + k * 32 + (int)lane;
                buf[k] = (idx < ROWF4) ? __ldg(row + idx)
                                       : make_float4(0.f, 0.f, 0.f, 0.f);
            }
#pragma unroll
            for (int k = 0; k < CHUNK; k++) {
                float4 v = buf[k];
                bool any = (v.x != 0.f) | (v.y != 0.f) | (v.z != 0.f) | (v.w != 0.f);
                if (__ballot_sync(0xffffffffu, any) == 0u) continue;   // ~88% skip
                int idx4 = (b0 + k * 32 + (int)lane) * 4;
                float vv[4] = {v.x, v.y, v.z, v.w};
#pragma unroll
                for (int cc = 0; cc < 4; cc++) {
                    unsigned m = __ballot_sync(0xffffffffu, vv[cc] != 0.0f);
                    if (m == 0u) continue;
                    if (vv[cc] != 0.0f) {
                        unsigned pos = cnt + (unsigned)__popc(m & ((1u << lane) - 1u));
                        if (pos < ROWCAP) lp[pos] = (unsigned short)(idx4 + cc);
                    }
                    cnt += (unsigned)__popc(m);   // warp-uniform update
                }
            }
        }

        if (lane == 0u) g_rowcnt[r] = (cnt > ROWCAP) ? ROWCAP : cnt;
        __threadfence();     // every lane orders its own slot stores
        __syncwarp();        // execution + memory ordering across the warp
        if (lane == 0u) atomicAdd(&g_rows_done[r / EE], 1u);   // release progress
    }
}

// ---------------- consumer role: 29 sequential SIR steps ----------------
__device__ void do_sim(const float* __restrict__ beta,
                       const float* __restrict__ gamma,
                       float* __restrict__ out) {
    const int tid   = threadIdx.x;
    const int gidx  = blockIdx.x * TPB + tid;        // 0 .. NSIM*TPB-1
    const int GS    = NSIM * TPB;
    const int gwarp = gidx >> 5;                     // 0 .. NSIM*8-1
    const int NW    = NSIM * (TPB / 32);
    const unsigned lane = (unsigned)tid & 31u;
    unsigned gen = 0;

    for (int t = 0; t < TT; t++) {
        // wait until extraction finished all EE rows of step t
        if (tid == 0) {
            while (atomicAdd(&g_rows_done[t], 0u) < (unsigned)EE) __nanosleep(256);
        }
        __syncthreads();
        __threadfence();                             // acquire list writes

        // phase A (fused SpMV pair, warp-per-edge):
        //   y_e = popcount(ballot(inf[n] != 0))  -- inf is 0/1, exact
        //   then z[n] += y_e for every n in row e.
        for (int e = gwarp; e < EE; e += NW) {
            unsigned r = (unsigned)t * EE + (unsigned)e;
            unsigned c = g_rowcnt[r];
            const unsigned short* lp = g_list + (size_t)r * ROWCAP;
            unsigned isum = 0u;
            for (unsigned i0 = 0; i0 < c; i0 += 32) {
                unsigned i = i0 + lane;
                bool inf = (i < c) && (g_inf[lp[i]] != 0.0f);
                isum += (unsigned)__popc(__ballot_sync(0xffffffffu, inf));
            }
            if (isum != 0u) {
                float ysum = (float)isum;            // small integer: exact
                for (unsigned i0 = 0; i0 < c; i0 += 32) {
                    unsigned i = i0 + lane;
                    if (i < c) atomicAdd(&g_z[lp[i]], ysum);
                }
            }
        }
        sim_barrier(gen);

        // phase B: node update (probabilities + stochastic state machine)
        for (int n = gidx; n < NN; n += GS) {
            float z = g_z[n];
            g_z[n] = 0.0f;

            const size_t PROW = (size_t)t * NN * 3 + (size_t)n * 3;
            const size_t SROW = (size_t)(30 + t) * NN * 3 + (size_t)n * 3;
            float pp0 = out[PROW + 0], pp1 = out[PROW + 1], pp2 = out[PROW + 2];
            float s0  = out[SROW + 0], s1  = out[SROW + 1];

            // Exact-rounding chain, no fmad contraction (matches XLA)
            float nc = __fmul_rn(beta[n],  z);
            float nr = __fmul_rn(gamma[n], s1);
            float p0 = __fsub_rn(pp0, nc);
            float p1 = __fsub_rn(__fadd_rn(pp1, nc), nr);
            float p2 = __fadd_rn(pp2, nr);
            p0 = fminf(fmaxf(p0, 0.0f), 1.0f);
            p1 = fminf(fmaxf(p1, 0.0f), 1.0f);
            p2 = fminf(fmaxf(p2, 0.0f), 1.0f);

            size_t POUT = (size_t)(t + 1) * NN * 3 + (size_t)n * 3;
            out[POUT + 0] = p0; out[POUT + 1] = p1; out[POUT + 2] = p2;

            uint2 k1 = g_k1[t], k2 = g_k2[t];
            unsigned o0, o1;
            tf2x32(k1.x, k1.y, 0u, (unsigned)n, o0, o1);
            float u1 = bits_to_uniform(o0 ^ o1);
            tf2x32(k2.x, k2.y, 0u, (unsigned)n, o0, o1);
            float u2 = bits_to_uniform(o0 ^ o1);

            bool wasS   = (s0 == 1.0f);
            bool wasI   = (s1 == 1.0f);
            bool s_to_I = wasS && (u1 < p1);
            bool i_ev   = wasI && (u1 < p2);
            bool i_to_R = i_ev && (u2 < 0.5f);
            bool i_to_S = i_ev && !(u2 < 0.5f);
            bool nS = (wasS && !s_to_I) || i_to_S;
            bool nI = s_to_I || (wasI && !i_ev);
            bool nR = (!wasS && !wasI) || i_to_R;

            size_t SOUT = (size_t)(30 + t + 1) * NN * 3 + (size_t)n * 3;
            float fI = nI ? 1.0f : 0.0f;
            out[SOUT + 0] = nS ? 1.0f : 0.0f;
            out[SOUT + 1] = fI;
            out[SOUT + 2] = nR ? 1.0f : 0.0f;
            g_inf[n] = fI;
        }
        sim_barrier(gen);   // inf/z visible before next step's phase A
    }
}

// ---------------- fused persistent kernel: overlap extraction with simulation ----
// Sim blocks are bids 0..NSIM-1 (scheduled first => guaranteed resident).
// Extraction blocks never wait on sim, so stragglers can't deadlock.
__global__ void __launch_bounds__(TPB, 2)
k_fused(const float* __restrict__ H,
        const float* __restrict__ beta,
        const float* __restrict__ gamma,
        float* __restrict__ out) {
    if (blockIdx.x < NSIM) do_sim(beta, gamma, out);
    else                   do_extract(H);
}

// ---------------- launch ----------------
extern "C" void kernel_launch(void* const* d_in, const int* in_sizes, int n_in,
                              void* d_out, int out_size) {
    const float* x     = (const float*)d_in[0];  // (N,3)
    const float* H     = (const float*)d_in[1];  // (29, E, N)
    const float* beta  = (const float*)d_in[2];  // (N,)
    const float* gamma = (const float*)d_in[3];  // (N,)
    float* out = (float*)d_out;                  // pathogen (30,N,3) then state (30,N,3)

    (void)in_sizes; (void)n_in; (void)out_size;

    k_init<<<(NN * 3 + 127) / 128, 128>>>(x, out);
    k_fused<<<NBLK, TPB>>>(H, beta, gamma, out);
}